// round 1
// baseline (speedup 1.0000x reference)
#include <cuda_runtime.h>
#include <cuda_bf16.h>

// SphericalContraction (MipNeRF-360 eq. 10) + per-point 3x3 Jacobian.
//
//   m = ||p||
//   m <= 1 : out = p            J = I
//   m >  1 : s = 2/m - 1/m^2    out = s*p
//            c = 2(1-m)/m^4     J = s*I + c * p p^T
//
// Output layout (out_size = N*12 floats):
//   [0, 3N)      contracted points, row-major [N,3]
//   [3N, 12N)    jacobians, row-major [N,3,3]
//
// Each thread processes 4 consecutive points so that every global access is a
// 16-byte (float4) transaction: 3 loads + 3 contracted stores + 9 jacobian
// stores per thread, all fully coalesced.

__device__ __forceinline__ void contract_point(float x, float y, float z,
                                               float* oc, float* oj) {
    float m2 = fmaf(x, x, fmaf(y, y, z * z));
    bool inside = (m2 <= 1.0f);           // m <= 1  <=>  m^2 <= 1 (no NaN risk)

    float inv  = rsqrtf(m2);              // 1/m   (garbage if m2==0; unused then)
    float m    = m2 * inv;                // m
    float s    = inv * (2.0f - inv);      // 2/m - 1/m^2
    float inv2 = inv * inv;
    float c    = 2.0f * (1.0f - m) * inv2 * inv2;  // 2(1-m)/m^4

    if (inside) { s = 1.0f; c = 0.0f; }   // out = p, J = I

    oc[0] = s * x;
    oc[1] = s * y;
    oc[2] = s * z;

    float cx = c * x, cy = c * y, cz = c * z;
    oj[0] = fmaf(cx, x, s);  oj[1] = cx * y;           oj[2] = cx * z;
    oj[3] = cy * x;          oj[4] = fmaf(cy, y, s);   oj[5] = cy * z;
    oj[6] = cz * x;          oj[7] = cz * y;           oj[8] = fmaf(cz, z, s);
}

// 4 points per thread; all global traffic via float4.
__global__ void __launch_bounds__(256)
contract_jac_vec4_kernel(const float4* __restrict__ xin,
                         float4* __restrict__ out_c,   // 3N floats
                         float4* __restrict__ out_j,   // 9N floats (offset 3N)
                         int nquads) {
    int t = blockIdx.x * blockDim.x + threadIdx.x;
    if (t >= nquads) return;

    float4 a = xin[3 * t + 0];
    float4 b = xin[3 * t + 1];
    float4 d = xin[3 * t + 2];

    float in[12] = {a.x, a.y, a.z, a.w, b.x, b.y, b.z, b.w, d.x, d.y, d.z, d.w};
    float oc[12];
    float oj[36];

#pragma unroll
    for (int p = 0; p < 4; ++p) {
        contract_point(in[3 * p + 0], in[3 * p + 1], in[3 * p + 2],
                       &oc[3 * p], &oj[9 * p]);
    }

#pragma unroll
    for (int k = 0; k < 3; ++k)
        out_c[3 * t + k] = make_float4(oc[4 * k], oc[4 * k + 1],
                                       oc[4 * k + 2], oc[4 * k + 3]);
#pragma unroll
    for (int k = 0; k < 9; ++k)
        out_j[9 * t + k] = make_float4(oj[4 * k], oj[4 * k + 1],
                                       oj[4 * k + 2], oj[4 * k + 3]);
}

// Scalar tail (and contract-only fallback) for any non-multiple-of-4 remainder.
__global__ void contract_jac_tail_kernel(const float* __restrict__ xin,
                                         float* __restrict__ out_c,
                                         float* __restrict__ out_j,  // may be null
                                         int start, int n) {
    int i = start + blockIdx.x * blockDim.x + threadIdx.x;
    if (i >= n) return;
    float oc[3], oj[9];
    contract_point(xin[3 * i], xin[3 * i + 1], xin[3 * i + 2], oc, oj);
#pragma unroll
    for (int k = 0; k < 3; ++k) out_c[3 * i + k] = oc[k];
    if (out_j) {
#pragma unroll
        for (int k = 0; k < 9; ++k) out_j[9 * i + k] = oj[k];
    }
}

extern "C" void kernel_launch(void* const* d_in, const int* in_sizes, int n_in,
                              void* d_out, int out_size) {
    const float* x = (const float*)d_in[0];
    int n = in_sizes[0] / 3;                 // number of points
    float* out_c = (float*)d_out;
    bool want_jac = (out_size >= 12 * n);    // tuple output: points + jacobian
    float* out_j = want_jac ? out_c + 3 * (size_t)n : nullptr;

    if (want_jac) {
        int nquads = n / 4;
        if (nquads > 0) {
            int threads = 256;
            int blocks = (nquads + threads - 1) / threads;
            contract_jac_vec4_kernel<<<blocks, threads>>>(
                (const float4*)x, (float4*)out_c, (float4*)out_j, nquads);
        }
        int done = nquads * 4;
        if (done < n) {
            int rem = n - done;
            contract_jac_tail_kernel<<<(rem + 255) / 256, 256>>>(
                x, out_c, out_j, done, n);
        }
    } else {
        contract_jac_tail_kernel<<<(n + 255) / 256, 256>>>(
            x, out_c, nullptr, 0, n);
    }
}

// round 2
// speedup vs baseline: 2.0287x; 2.0287x over previous
#include <cuda_runtime.h>
#include <cuda_bf16.h>

// SphericalContraction (MipNeRF-360 eq. 10) + per-point 3x3 Jacobian.
//
//   m = ||p||
//   m <= 1 : out = p            J = I
//   m >  1 : s = 2/m - 1/m^2    out = s*p
//            c = 2(1-m)/m^4     J = s*I + c * p p^T
//
// Output layout (out_size = N*12 floats):
//   [0, 3N)   contracted points [N,3]
//   [3N,12N)  jacobians [N,3,3]
//
// R2: smem-staged version. All DRAM traffic (input load + jacobian store) is
// lane-consecutive float4 — no L1 wavefront amplification. Strided per-thread
// point assignment (q = tid + 256*j) makes all smem access conflict-free
// (strides 3 and 9 are coprime with 32).

#define PTS_PER_BLOCK 1024
#define THREADS 256

__device__ __forceinline__ void contract_sc(float x, float y, float z,
                                            float& s, float& c) {
    float m2 = fmaf(x, x, fmaf(y, y, z * z));
    bool inside = (m2 <= 1.0f);          // m <= 1  <=>  m^2 <= 1 (no NaN risk)
    float inv  = rsqrtf(m2);             // 1/m (garbage if m2==0; unused then)
    float m    = m2 * inv;               // m
    s          = inv * (2.0f - inv);     // 2/m - 1/m^2
    float inv2 = inv * inv;
    c          = 2.0f * (1.0f - m) * inv2 * inv2;  // 2(1-m)/m^4
    if (inside) { s = 1.0f; c = 0.0f; }  // out = p, J = I
}

__global__ void __launch_bounds__(THREADS)
contract_jac_smem_kernel(const float4* __restrict__ xin4,
                         float* __restrict__ out_c,    // 3N floats
                         float4* __restrict__ out_j4)  // 9N floats as float4
{
    __shared__ float s_in[3 * PTS_PER_BLOCK];   // 12 KB
    __shared__ float s_j[9 * PTS_PER_BLOCK];    // 36 KB

    const int tid = threadIdx.x;
    const size_t base = (size_t)blockIdx.x * PTS_PER_BLOCK;

    // ---- coalesced input load: 3*1024 floats = 768 float4, 3 per thread ----
    const float4* src = xin4 + base * 3 / 4;     // base*3 divisible by 4
    float4* s_in4 = (float4*)s_in;
#pragma unroll
    for (int i = 0; i < 3; ++i)
        s_in4[tid + THREADS * i] = src[tid + THREADS * i];
    __syncthreads();

    // ---- compute 4 points per thread, strided q = tid + 256*j ----
#pragma unroll
    for (int j = 0; j < 4; ++j) {
        int q = tid + THREADS * j;
        float x = s_in[3 * q + 0];
        float y = s_in[3 * q + 1];
        float z = s_in[3 * q + 2];

        float s, c;
        contract_sc(x, y, z, s, c);

        // contracted point: direct scalar stores (stride-12B across lanes;
        // covers exactly the sectors the 384B/warp range needs)
        size_t g = base + (size_t)q;
        out_c[3 * g + 0] = s * x;
        out_c[3 * g + 1] = s * y;
        out_c[3 * g + 2] = s * z;

        // jacobian into smem (stride 9 -> conflict-free)
        float cx = c * x, cy = c * y, cz = c * z;
        float* jr = &s_j[9 * q];
        jr[0] = fmaf(cx, x, s);  jr[1] = cx * y;          jr[2] = cx * z;
        jr[3] = cy * x;          jr[4] = fmaf(cy, y, s);  jr[5] = cy * z;
        jr[6] = cz * x;          jr[7] = cz * y;          jr[8] = fmaf(cz, z, s);
    }
    __syncthreads();

    // ---- coalesced jacobian store: 9*1024 floats = 2304 float4, 9/thread ----
    const float4* s_j4 = (const float4*)s_j;
    float4* dst = out_j4 + base * 9 / 4;         // base*9 divisible by 4
#pragma unroll
    for (int i = 0; i < 9; ++i)
        dst[tid + THREADS * i] = s_j4[tid + THREADS * i];
}

// Scalar tail / contract-only fallback.
__global__ void contract_jac_tail_kernel(const float* __restrict__ xin,
                                         float* __restrict__ out_c,
                                         float* __restrict__ out_j,  // may be null
                                         int start, int n) {
    int i = start + blockIdx.x * blockDim.x + threadIdx.x;
    if (i >= n) return;
    float x = xin[3 * i], y = xin[3 * i + 1], z = xin[3 * i + 2];
    float s, c;
    contract_sc(x, y, z, s, c);
    out_c[3 * i + 0] = s * x;
    out_c[3 * i + 1] = s * y;
    out_c[3 * i + 2] = s * z;
    if (out_j) {
        float cx = c * x, cy = c * y, cz = c * z;
        float* jr = &out_j[9 * (size_t)i];
        jr[0] = fmaf(cx, x, s);  jr[1] = cx * y;          jr[2] = cx * z;
        jr[3] = cy * x;          jr[4] = fmaf(cy, y, s);  jr[5] = cy * z;
        jr[6] = cz * x;          jr[7] = cz * y;          jr[8] = fmaf(cz, z, s);
    }
}

extern "C" void kernel_launch(void* const* d_in, const int* in_sizes, int n_in,
                              void* d_out, int out_size) {
    const float* x = (const float*)d_in[0];
    int n = in_sizes[0] / 3;                 // number of points
    float* out_c = (float*)d_out;
    bool want_jac = (out_size >= 12 * n);
    float* out_j = want_jac ? out_c + 3 * (size_t)n : nullptr;

    if (want_jac) {
        int nfull = n / PTS_PER_BLOCK;
        if (nfull > 0) {
            contract_jac_smem_kernel<<<nfull, THREADS>>>(
                (const float4*)x, out_c, (float4*)(out_j));
        }
        int done = nfull * PTS_PER_BLOCK;
        if (done < n) {
            int rem = n - done;
            contract_jac_tail_kernel<<<(rem + 255) / 256, 256>>>(
                x, out_c, out_j, done, n);
        }
    } else {
        contract_jac_tail_kernel<<<(n + 255) / 256, 256>>>(
            x, out_c, nullptr, 0, n);
    }
}

// round 3
// speedup vs baseline: 2.1274x; 1.0486x over previous
#include <cuda_runtime.h>
#include <cuda_bf16.h>

// SphericalContraction (MipNeRF-360 eq. 10) + per-point 3x3 Jacobian.
//
//   m = ||p||
//   m <= 1 : out = p            J = I
//   m >  1 : s = 2/m - 1/m^2    out = s*p
//            c = 2(1-m)/m^4     J = s*I + c * p p^T
//
// Output layout (out_size = N*12 floats):
//   [0, 3N)   contracted points [N,3]
//   [3N,12N)  jacobians [N,3,3]
//
// R3: every global transaction is a lane-consecutive float4 (input load,
// contracted-point store, jacobian store). Contracted points are staged in
// smem by reusing the input buffer after all compute reads complete.
// 24 KB smem/block -> 8 blocks/SM -> 100% occupancy.

#define PTS_PER_BLOCK 512
#define THREADS 256

__device__ __forceinline__ void contract_sc(float x, float y, float z,
                                            float& s, float& c) {
    float m2 = fmaf(x, x, fmaf(y, y, z * z));
    bool inside = (m2 <= 1.0f);          // m <= 1  <=>  m^2 <= 1 (no NaN risk)
    float inv  = rsqrtf(m2);             // 1/m (garbage if m2==0; unused then)
    float m    = m2 * inv;               // m
    s          = inv * (2.0f - inv);     // 2/m - 1/m^2
    float inv2 = inv * inv;
    c          = 2.0f * (1.0f - m) * inv2 * inv2;  // 2(1-m)/m^4
    if (inside) { s = 1.0f; c = 0.0f; }  // out = p, J = I
}

__global__ void __launch_bounds__(THREADS)
contract_jac_smem_kernel(const float4* __restrict__ xin4,
                         float4* __restrict__ out_c4,  // 3N floats as float4
                         float4* __restrict__ out_j4)  // 9N floats as float4
{
    __shared__ float s_in[3 * PTS_PER_BLOCK];   // 6 KB (reused for out_c)
    __shared__ float s_j[9 * PTS_PER_BLOCK];    // 18 KB

    const int tid = threadIdx.x;
    const size_t base = (size_t)blockIdx.x * PTS_PER_BLOCK;

    // ---- coalesced input load: 3*512 floats = 384 float4 ----
    const float4* src = xin4 + base * 3 / 4;
    float4* s_in4 = (float4*)s_in;
    s_in4[tid] = src[tid];
    if (tid < 128) s_in4[256 + tid] = src[256 + tid];
    __syncthreads();

    // ---- compute 2 points per thread (q = tid, tid+256) ----
    float oc[6];
#pragma unroll
    for (int j = 0; j < 2; ++j) {
        int q = tid + THREADS * j;
        float x = s_in[3 * q + 0];     // stride 3: conflict-free
        float y = s_in[3 * q + 1];
        float z = s_in[3 * q + 2];

        float s, c;
        contract_sc(x, y, z, s, c);

        oc[3 * j + 0] = s * x;
        oc[3 * j + 1] = s * y;
        oc[3 * j + 2] = s * z;

        float cx = c * x, cy = c * y, cz = c * z;
        float* jr = &s_j[9 * q];       // stride 9: conflict-free
        jr[0] = fmaf(cx, x, s);  jr[1] = cx * y;          jr[2] = cx * z;
        jr[3] = cy * x;          jr[4] = fmaf(cy, y, s);  jr[5] = cy * z;
        jr[6] = cz * x;          jr[7] = cz * y;          jr[8] = fmaf(cz, z, s);
    }
    __syncthreads();   // all s_in reads done; s_j complete

    // ---- coalesced jacobian store: 9*512 floats = 1152 float4 ----
    const float4* s_j4 = (const float4*)s_j;
    float4* dstj = out_j4 + base * 9 / 4;
#pragma unroll
    for (int i = 0; i < 4; ++i)
        dstj[tid + THREADS * i] = s_j4[tid + THREADS * i];
    if (tid < 128) dstj[tid + THREADS * 4] = s_j4[tid + THREADS * 4];

    // ---- stage contracted points into s_in (safe: reads finished) ----
#pragma unroll
    for (int j = 0; j < 2; ++j) {
        int q = tid + THREADS * j;
        s_in[3 * q + 0] = oc[3 * j + 0];
        s_in[3 * q + 1] = oc[3 * j + 1];
        s_in[3 * q + 2] = oc[3 * j + 2];
    }
    __syncthreads();

    // ---- coalesced contracted store: 384 float4 ----
    float4* dstc = out_c4 + base * 3 / 4;
    dstc[tid] = s_in4[tid];
    if (tid < 128) dstc[256 + tid] = s_in4[256 + tid];
}

// Scalar tail / contract-only fallback.
__global__ void contract_jac_tail_kernel(const float* __restrict__ xin,
                                         float* __restrict__ out_c,
                                         float* __restrict__ out_j,  // may be null
                                         int start, int n) {
    int i = start + blockIdx.x * blockDim.x + threadIdx.x;
    if (i >= n) return;
    float x = xin[3 * i], y = xin[3 * i + 1], z = xin[3 * i + 2];
    float s, c;
    contract_sc(x, y, z, s, c);
    out_c[3 * i + 0] = s * x;
    out_c[3 * i + 1] = s * y;
    out_c[3 * i + 2] = s * z;
    if (out_j) {
        float cx = c * x, cy = c * y, cz = c * z;
        float* jr = &out_j[9 * (size_t)i];
        jr[0] = fmaf(cx, x, s);  jr[1] = cx * y;          jr[2] = cx * z;
        jr[3] = cy * x;          jr[4] = fmaf(cy, y, s);  jr[5] = cy * z;
        jr[6] = cz * x;          jr[7] = cz * y;          jr[8] = fmaf(cz, z, s);
    }
}

extern "C" void kernel_launch(void* const* d_in, const int* in_sizes, int n_in,
                              void* d_out, int out_size) {
    const float* x = (const float*)d_in[0];
    int n = in_sizes[0] / 3;                 // number of points
    float* out_c = (float*)d_out;
    bool want_jac = (out_size >= 12 * n);
    float* out_j = want_jac ? out_c + 3 * (size_t)n : nullptr;

    if (want_jac) {
        int nfull = n / PTS_PER_BLOCK;
        if (nfull > 0) {
            contract_jac_smem_kernel<<<nfull, THREADS>>>(
                (const float4*)x, (float4*)out_c, (float4*)out_j);
        }
        int done = nfull * PTS_PER_BLOCK;
        if (done < n) {
            int rem = n - done;
            contract_jac_tail_kernel<<<(rem + 255) / 256, 256>>>(
                x, out_c, out_j, done, n);
        }
    } else {
        contract_jac_tail_kernel<<<(n + 255) / 256, 256>>>(
            x, out_c, nullptr, 0, n);
    }
}